// round 1
// baseline (speedup 1.0000x reference)
#include <cuda_runtime.h>

#define NN 100000
#define NE 1600000
#define FD 128
#define NG 128
#define FO 64

// ---------------- device scratch (no allocations allowed) ----------------
__device__ __align__(16) float d_hs[NN * FD];    // h * dinv (per layer)
__device__ __align__(16) float d_agg[NN * FD];   // scatter accumulator
__device__ __align__(16) float d_z[NN * FD];     // pre-BN layer output
__device__ float d_dinv[NN];
__device__ int   d_degcnt[NN];
__device__ float d_stats[4 * FD];                // layer0: [0..256), layer1: [256..512)
__device__ float d_bnscale[2 * FD];
__device__ float d_bnshift[2 * FD];
__device__ __align__(16) float d_pooled[NG * FD];
__device__ int   d_gcnt[NG];
__device__ int   d_is64;

// ---------------- helpers ----------------
__device__ __forceinline__ unsigned long long pack2(float lo, float hi) {
    unsigned long long r;
    asm("mov.b64 %0, {%1, %2};" : "=l"(r) : "f"(lo), "f"(hi));
    return r;
}
__device__ __forceinline__ float2 unpack2(unsigned long long v) {
    float2 r;
    asm("mov.b64 {%0, %1}, %2;" : "=f"(r.x), "=f"(r.y) : "l"(v));
    return r;
}
__device__ __forceinline__ void fma2(unsigned long long& d, unsigned long long a, unsigned long long b) {
    asm("fma.rn.f32x2 %0, %1, %2, %0;" : "+l"(d) : "l"(a), "l"(b));
}
__device__ __forceinline__ int load_idx(const void* p, long long i) {
    if (d_is64) return (int)((const long long*)p)[i];
    return ((const int*)p)[i];
}
__device__ __forceinline__ void red_add_v4(float* dst, float4 v) {
    asm volatile("red.global.add.v4.f32 [%0], {%1, %2, %3, %4};"
                 :: "l"(dst), "f"(v.x), "f"(v.y), "f"(v.z), "f"(v.w) : "memory");
}

// ---------------- kernels ----------------

// Detect int64 vs int32 indices: int64 values < 2^32 => every odd 32-bit word is 0.
__global__ void detect_kernel(const unsigned int* ei32) {
    if (threadIdx.x == 0) {
        int is64 = 1;
        for (int i = 0; i < 128; i++) {
            if (ei32[2 * i + 1] != 0u) { is64 = 0; break; }
        }
        d_is64 = is64;
    }
}

__global__ void zero_misc_kernel() {
    int i = blockIdx.x * blockDim.x + threadIdx.x;
    if (i < NN) d_degcnt[i] = 0;
    if (i < 4 * FD) d_stats[i] = 0.0f;
    if (i < NG * FD) d_pooled[i] = 0.0f;
    if (i < NG) d_gcnt[i] = 0;
}

__global__ void zero_agg_kernel() {
    int i = blockIdx.x * blockDim.x + threadIdx.x;   // over NN*FD/4 float4s
    ((float4*)d_agg)[i] = make_float4(0.f, 0.f, 0.f, 0.f);
}

__global__ void deg_kernel(const void* ei) {
    int i = blockIdx.x * blockDim.x + threadIdx.x;
    if (i < NE) atomicAdd(&d_degcnt[load_idx(ei, (long long)NE + i)], 1);
}

__global__ void gcount_kernel(const void* batch) {
    int i = blockIdx.x * blockDim.x + threadIdx.x;
    if (i < NN) atomicAdd(&d_gcnt[load_idx(batch, i)], 1);
}

__global__ void dinv_kernel() {
    int i = blockIdx.x * blockDim.x + threadIdx.x;
    if (i < NN) d_dinv[i] = rsqrtf((float)(d_degcnt[i] + 1));
}

// out (d_hs) = rowscale(dinv) * ( bnrelu?(A) @ W ), tile 128x128, BK=16, f32x2 FMA.
// layer==0: A = Aext (x), no BN.  layer==1: A = d_z with BN(scale/shift idx 0)+ReLU on load.
__global__ __launch_bounds__(256) void gemm_kernel(const float* __restrict__ Aext,
                                                   const float* __restrict__ W,
                                                   int layer) {
    __shared__ float As[16][132];   // [k][m], padded: 132*4 bytes keeps 16B alignment
    __shared__ float Ws[16][128];   // [k][n]

    const float* A = (layer == 0) ? Aext : d_z;
    int tid = threadIdx.x;
    int tx = tid & 15, ty = tid >> 4;
    int bm = blockIdx.x * 128;

    unsigned long long acc[8][4];
#pragma unroll
    for (int r = 0; r < 8; r++)
#pragma unroll
        for (int c = 0; c < 4; c++) acc[r][c] = 0ull;

    for (int k0 = 0; k0 < FD; k0 += 16) {
        __syncthreads();
        // load W chunk [16][128]
#pragma unroll
        for (int r = 0; r < 2; r++) {
            int idx = tid * 2 + r;
            int kk = idx >> 5;
            int n = (idx & 31) << 2;
            float4 w = *(const float4*)(W + (k0 + kk) * FD + n);
            *(float4*)&Ws[kk][n] = w;
        }
        // load A chunk [128 rows][16 cols], transposed into As[k][m]
#pragma unroll
        for (int r = 0; r < 2; r++) {
            int idx = tid * 2 + r;
            int m = idx >> 2;
            int c = (idx & 3) << 2;
            int row = bm + m;
            float4 v = make_float4(0.f, 0.f, 0.f, 0.f);
            if (row < NN) v = *(const float4*)(A + (long long)row * FD + k0 + c);
            if (layer == 1) {
                int f = k0 + c;
                float4 sc = *(const float4*)&d_bnscale[f];
                float4 sh = *(const float4*)&d_bnshift[f];
                v.x = fmaxf(fmaf(v.x, sc.x, sh.x), 0.f);
                v.y = fmaxf(fmaf(v.y, sc.y, sh.y), 0.f);
                v.z = fmaxf(fmaf(v.z, sc.z, sh.z), 0.f);
                v.w = fmaxf(fmaf(v.w, sc.w, sh.w), 0.f);
            }
            As[c + 0][m] = v.x;
            As[c + 1][m] = v.y;
            As[c + 2][m] = v.z;
            As[c + 3][m] = v.w;
        }
        __syncthreads();

#pragma unroll
        for (int kk = 0; kk < 16; kk++) {
            float4 a0 = *(float4*)&As[kk][ty * 8];
            float4 a1 = *(float4*)&As[kk][ty * 8 + 4];
            float4 b0 = *(float4*)&Ws[kk][tx * 8];
            float4 b1 = *(float4*)&Ws[kk][tx * 8 + 4];
            unsigned long long ap[8];
            ap[0] = pack2(a0.x, a0.x); ap[1] = pack2(a0.y, a0.y);
            ap[2] = pack2(a0.z, a0.z); ap[3] = pack2(a0.w, a0.w);
            ap[4] = pack2(a1.x, a1.x); ap[5] = pack2(a1.y, a1.y);
            ap[6] = pack2(a1.z, a1.z); ap[7] = pack2(a1.w, a1.w);
            unsigned long long bp[4];
            bp[0] = pack2(b0.x, b0.y); bp[1] = pack2(b0.z, b0.w);
            bp[2] = pack2(b1.x, b1.y); bp[3] = pack2(b1.z, b1.w);
#pragma unroll
            for (int r = 0; r < 8; r++)
#pragma unroll
                for (int c = 0; c < 4; c++) fma2(acc[r][c], ap[r], bp[c]);
        }
    }

    // epilogue: hs = dinv[row] * result
#pragma unroll
    for (int r = 0; r < 8; r++) {
        int row = bm + ty * 8 + r;
        if (row < NN) {
            float dv = d_dinv[row];
            float2 p0 = unpack2(acc[r][0]);
            float2 p1 = unpack2(acc[r][1]);
            float2 p2 = unpack2(acc[r][2]);
            float2 p3 = unpack2(acc[r][3]);
            float4 o0 = make_float4(p0.x * dv, p0.y * dv, p1.x * dv, p1.y * dv);
            float4 o1 = make_float4(p2.x * dv, p2.y * dv, p3.x * dv, p3.y * dv);
            float* outp = d_hs + (long long)row * FD + tx * 8;
            *(float4*)outp = o0;
            *(float4*)(outp + 4) = o1;
        }
    }
}

// warp per edge: agg[dst] += hs[src]  (128 floats via 32 lanes x v4 red)
__global__ __launch_bounds__(256) void scatter_kernel(const void* ei) {
    long long gt = (long long)blockIdx.x * blockDim.x + threadIdx.x;
    long long e = gt >> 5;
    int lane = threadIdx.x & 31;
    if (e >= NE) return;
    int s = load_idx(ei, e);
    int d = load_idx(ei, (long long)NE + e);
    float4 v = __ldg((const float4*)(d_hs + (long long)s * FD) + lane);
    red_add_v4(d_agg + (long long)d * FD + lane * 4, v);
}

// z = dinv*(agg + hs) + bias ; accumulate per-feature sum & sumsq for BN
__global__ __launch_bounds__(256) void finalize_kernel(const float* __restrict__ bias, int statoff) {
    int f = threadIdx.x & 127;
    int sub = threadIdx.x >> 7;       // 0/1
    int base = blockIdx.x * 128;
    float b = bias[f];
    float s = 0.f, q = 0.f;
#pragma unroll 4
    for (int i = 0; i < 64; i++) {
        int r = base + sub + 2 * i;
        if (r < NN) {
            long long off = (long long)r * FD + f;
            float v = d_dinv[r] * (d_agg[off] + d_hs[off]) + b;
            d_z[off] = v;
            s += v;
            q += v * v;
        }
    }
    atomicAdd(&d_stats[statoff + f], s);
    atomicAdd(&d_stats[statoff + FD + f], q);
}

__global__ void bnparams_kernel(const float* __restrict__ g, const float* __restrict__ be, int layer) {
    int f = threadIdx.x;
    if (f < FD) {
        float inv_n = 1.0f / (float)NN;
        float mu = d_stats[layer * 256 + f] * inv_n;
        float ms = d_stats[layer * 256 + FD + f] * inv_n;
        float var = ms - mu * mu;
        float istd = rsqrtf(var + 1e-5f);
        float sc = g[f] * istd;
        d_bnscale[layer * FD + f] = sc;
        d_bnshift[layer * FD + f] = be[f] - mu * sc;
    }
}

// warp per node: pooled[batch[n]] += relu(bn2(z[n]))
__global__ __launch_bounds__(256) void pool_kernel(const void* batch) {
    long long gt = (long long)blockIdx.x * blockDim.x + threadIdx.x;
    long long n = gt >> 5;
    int lane = threadIdx.x & 31;
    if (n >= NN) return;
    int g = load_idx(batch, n);
    int f = lane * 4;
    float4 v = *(const float4*)(d_z + n * FD + f);
    float4 sc = *(const float4*)&d_bnscale[FD + f];
    float4 sh = *(const float4*)&d_bnshift[FD + f];
    v.x = fmaxf(fmaf(v.x, sc.x, sh.x), 0.f);
    v.y = fmaxf(fmaf(v.y, sc.y, sh.y), 0.f);
    v.z = fmaxf(fmaf(v.z, sc.z, sh.z), 0.f);
    v.w = fmaxf(fmaf(v.w, sc.w, sh.w), 0.f);
    red_add_v4(d_pooled + (long long)g * FD + f, v);
}

// out[g][o] = (sum_h pooled[g][h] * Wout[h][o]) / max(cnt,1) + bout[o]
__global__ void out_kernel(const float* __restrict__ Wout, const float* __restrict__ bout,
                           float* __restrict__ out) {
    int g = blockIdx.x;
    int o = threadIdx.x;
    float inv = 1.0f / fmaxf((float)d_gcnt[g], 1.0f);
    float acc = 0.f;
#pragma unroll 8
    for (int h = 0; h < FD; h++) acc += d_pooled[g * FD + h] * Wout[h * FO + o];
    out[g * FO + o] = acc * inv + bout[o];
}

// ---------------- launch ----------------
extern "C" void kernel_launch(void* const* d_in, const int* in_sizes, int n_in,
                              void* d_out, int out_size) {
    int ii = 0;
    auto nxt = [&]() -> const void* {
        while (ii < n_in && in_sizes[ii] == 1) ii++;   // skip scalar (num_graphs) if present
        return d_in[ii++];
    };
    const float* x   = (const float*)nxt();
    const void*  ei  = nxt();
    const void*  bat = nxt();
    const float* W0  = (const float*)nxt();
    const float* b0  = (const float*)nxt();
    const float* g0  = (const float*)nxt();
    const float* be0 = (const float*)nxt();
    const float* W1  = (const float*)nxt();
    const float* b1  = (const float*)nxt();
    const float* g1  = (const float*)nxt();
    const float* be1 = (const float*)nxt();
    const float* Wo  = (const float*)nxt();
    const float* bo  = (const float*)nxt();
    float* out = (float*)d_out;

    detect_kernel<<<1, 32>>>((const unsigned int*)ei);
    zero_misc_kernel<<<(NN + 255) / 256, 256>>>();
    zero_agg_kernel<<<(NN * FD / 4) / 256, 256>>>();
    deg_kernel<<<(NE + 255) / 256, 256>>>(ei);
    gcount_kernel<<<(NN + 255) / 256, 256>>>(bat);
    dinv_kernel<<<(NN + 255) / 256, 256>>>();

    // layer 1
    gemm_kernel<<<(NN + 127) / 128, 256>>>(x, W0, 0);
    scatter_kernel<<<(int)(((long long)NE * 32) / 256), 256>>>(ei);
    finalize_kernel<<<(NN + 127) / 128, 256>>>(b0, 0);
    bnparams_kernel<<<1, 128>>>(g0, be0, 0);

    // layer 2
    zero_agg_kernel<<<(NN * FD / 4) / 256, 256>>>();
    gemm_kernel<<<(NN + 127) / 128, 256>>>(nullptr, W1, 1);
    scatter_kernel<<<(int)(((long long)NE * 32) / 256), 256>>>(ei);
    finalize_kernel<<<(NN + 127) / 128, 256>>>(b1, 256);
    bnparams_kernel<<<1, 128>>>(g1, be1, 1);

    // pool + output projection
    pool_kernel<<<(int)(((long long)NN * 32 + 255) / 256), 256>>>(bat);
    out_kernel<<<NG, FO>>>(Wo, bo, out);
}

// round 6
// speedup vs baseline: 1.5829x; 1.5829x over previous
#include <cuda_runtime.h>

#define NN 100000
#define NE 1600000
#define FD 128
#define NG 128
#define FO 64
#define NBLK 98            // ceil(NN/1024)
#define GPART 1024         // gather grid / #stat partials

// ---------------- device scratch ----------------
__device__ __align__(16) float d_hs[NN * FD];    // h (per layer, unscaled)
__device__ __align__(16) float d_z[NN * FD];     // pre-BN layer output
__device__ float d_dinv[NN];
__device__ int   d_degcnt[NN];
__device__ int   d_rowtmp[NN];
__device__ int   d_rs[NN + 1];
__device__ int   d_cur[NN];
__device__ int   d_csr[NE];
__device__ int   d_bsum[NBLK];
__device__ int   d_boff[128];
__device__ float d_part[GPART * 256];            // per-block BN stat partials [s(128) | q(128)]
__device__ float d_bnscale[2 * FD];
__device__ float d_bnshift[2 * FD];
__device__ __align__(16) float d_pooled[NG * FD];
__device__ int   d_gcnt[NG];
__device__ int   d_is64;

// ---------------- helpers ----------------
__device__ __forceinline__ unsigned long long pack2(float lo, float hi) {
    unsigned long long r;
    asm("mov.b64 %0, {%1, %2};" : "=l"(r) : "f"(lo), "f"(hi));
    return r;
}
__device__ __forceinline__ float2 unpack2(unsigned long long v) {
    float2 r;
    asm("mov.b64 {%0, %1}, %2;" : "=f"(r.x), "=f"(r.y) : "l"(v));
    return r;
}
__device__ __forceinline__ void fma2(unsigned long long& d, unsigned long long a, unsigned long long b) {
    asm("fma.rn.f32x2 %0, %1, %2, %0;" : "+l"(d) : "l"(a), "l"(b));
}
__device__ __forceinline__ int load_idx(const void* p, long long i) {
    if (d_is64) return (int)((const long long*)p)[i];
    return ((const int*)p)[i];
}
__device__ __forceinline__ void red_add_v4(float* dst, float4 v) {
    asm volatile("red.global.add.v4.f32 [%0], {%1, %2, %3, %4};"
                 :: "l"(dst), "f"(v.x), "f"(v.y), "f"(v.z), "f"(v.w) : "memory");
}

// ---------------- kernels ----------------

__global__ void detect_kernel(const unsigned int* ei32) {
    if (threadIdx.x == 0) {
        int is64 = 1;
        for (int i = 0; i < 128; i++)
            if (ei32[2 * i + 1] != 0u) { is64 = 0; break; }
        d_is64 = is64;
    }
}

__global__ void zero_misc_kernel() {
    int i = blockIdx.x * blockDim.x + threadIdx.x;
    if (i < NN) d_degcnt[i] = 0;
    if (i < NG * FD) d_pooled[i] = 0.0f;
    if (i < NG) d_gcnt[i] = 0;
}

__global__ void deg_kernel(const void* ei) {
    int i = blockIdx.x * blockDim.x + threadIdx.x;
    if (i < NE) atomicAdd(&d_degcnt[load_idx(ei, (long long)NE + i)], 1);
}

__global__ void gcount_kernel(const void* batch) {
    int i = blockIdx.x * blockDim.x + threadIdx.x;
    if (i < NN) atomicAdd(&d_gcnt[load_idx(batch, i)], 1);
}

// per-1024-block inclusive scan of degrees
__global__ void scanA_kernel() {
    __shared__ int sm[1024];
    int i = blockIdx.x * 1024 + threadIdx.x;
    int v = (i < NN) ? d_degcnt[i] : 0;
    sm[threadIdx.x] = v;
    __syncthreads();
#pragma unroll
    for (int off = 1; off < 1024; off <<= 1) {
        int t = (threadIdx.x >= off) ? sm[threadIdx.x - off] : 0;
        __syncthreads();
        sm[threadIdx.x] += t;
        __syncthreads();
    }
    if (i < NN) d_rowtmp[i] = sm[threadIdx.x];
    if (threadIdx.x == 1023) d_bsum[blockIdx.x] = sm[1023];
}

__global__ void scanB_kernel() {
    __shared__ int sm[128];
    int t = threadIdx.x;
    sm[t] = (t < NBLK) ? d_bsum[t] : 0;
    __syncthreads();
#pragma unroll
    for (int off = 1; off < 128; off <<= 1) {
        int v = (t >= off) ? sm[t - off] : 0;
        __syncthreads();
        sm[t] += v;
        __syncthreads();
    }
    d_boff[t] = sm[t];
}

// finalize row pointers, cursors, dinv
__global__ void scanC_kernel() {
    int i = blockIdx.x * 1024 + threadIdx.x;
    if (i >= NN) return;
    int blk = blockIdx.x;
    int off = (blk == 0) ? 0 : d_boff[blk - 1];
    int deg = d_degcnt[i];
    int incl = d_rowtmp[i] + off;
    d_rs[i + 1] = incl;
    d_cur[i] = incl - deg;
    d_dinv[i] = rsqrtf((float)(deg + 1));
    if (i == 0) d_rs[0] = 0;
}

__global__ void csr_fill_kernel(const void* ei) {
    int i = blockIdx.x * blockDim.x + threadIdx.x;
    if (i >= NE) return;
    int s = load_idx(ei, i);
    int d = load_idx(ei, (long long)NE + i);
    int pos = atomicAdd(&d_cur[d], 1);
    d_csr[pos] = s;
}

// h = bnrelu?(A) @ W   (tile 128x128, BK=16, f32x2 FMA)
__global__ __launch_bounds__(256) void gemm_kernel(const float* __restrict__ Aext,
                                                   const float* __restrict__ W,
                                                   int layer) {
    __shared__ float As[16][132];
    __shared__ float Ws[16][128];

    const float* A = (layer == 0) ? Aext : d_z;
    int tid = threadIdx.x;
    int tx = tid & 15, ty = tid >> 4;
    int bm = blockIdx.x * 128;

    unsigned long long acc[8][4];
#pragma unroll
    for (int r = 0; r < 8; r++)
#pragma unroll
        for (int c = 0; c < 4; c++) acc[r][c] = 0ull;

    for (int k0 = 0; k0 < FD; k0 += 16) {
        __syncthreads();
#pragma unroll
        for (int r = 0; r < 2; r++) {
            int idx = tid * 2 + r;
            int kk = idx >> 5;
            int n = (idx & 31) << 2;
            *(float4*)&Ws[kk][n] = *(const float4*)(W + (k0 + kk) * FD + n);
        }
#pragma unroll
        for (int r = 0; r < 2; r++) {
            int idx = tid * 2 + r;
            int m = idx >> 2;
            int c = (idx & 3) << 2;
            int row = bm + m;
            float4 v = make_float4(0.f, 0.f, 0.f, 0.f);
            if (row < NN) v = *(const float4*)(A + (long long)row * FD + k0 + c);
            if (layer == 1) {
                int f = k0 + c;
                float4 sc = *(const float4*)&d_bnscale[f];
                float4 sh = *(const float4*)&d_bnshift[f];
                v.x = fmaxf(fmaf(v.x, sc.x, sh.x), 0.f);
                v.y = fmaxf(fmaf(v.y, sc.y, sh.y), 0.f);
                v.z = fmaxf(fmaf(v.z, sc.z, sh.z), 0.f);
                v.w = fmaxf(fmaf(v.w, sc.w, sh.w), 0.f);
            }
            As[c + 0][m] = v.x;
            As[c + 1][m] = v.y;
            As[c + 2][m] = v.z;
            As[c + 3][m] = v.w;
        }
        __syncthreads();

#pragma unroll
        for (int kk = 0; kk < 16; kk++) {
            float4 a0 = *(float4*)&As[kk][ty * 8];
            float4 a1 = *(float4*)&As[kk][ty * 8 + 4];
            // B pairs loaded directly as 64-bit (already {lo,hi} layout)
            ulonglong2 w0 = *(ulonglong2*)&Ws[kk][tx * 8];
            ulonglong2 w1 = *(ulonglong2*)&Ws[kk][tx * 8 + 4];
            unsigned long long ap[8];
            ap[0] = pack2(a0.x, a0.x); ap[1] = pack2(a0.y, a0.y);
            ap[2] = pack2(a0.z, a0.z); ap[3] = pack2(a0.w, a0.w);
            ap[4] = pack2(a1.x, a1.x); ap[5] = pack2(a1.y, a1.y);
            ap[6] = pack2(a1.z, a1.z); ap[7] = pack2(a1.w, a1.w);
            unsigned long long bp[4] = {w0.x, w0.y, w1.x, w1.y};
#pragma unroll
            for (int r = 0; r < 8; r++)
#pragma unroll
                for (int c = 0; c < 4; c++) fma2(acc[r][c], ap[r], bp[c]);
        }
    }

#pragma unroll
    for (int r = 0; r < 8; r++) {
        int row = bm + ty * 8 + r;
        if (row < NN) {
            float2 p0 = unpack2(acc[r][0]);
            float2 p1 = unpack2(acc[r][1]);
            float2 p2 = unpack2(acc[r][2]);
            float2 p3 = unpack2(acc[r][3]);
            float* outp = d_hs + (long long)row * FD + tx * 8;
            *(float4*)outp = make_float4(p0.x, p0.y, p1.x, p1.y);
            *(float4*)(outp + 4) = make_float4(p2.x, p2.y, p3.x, p3.y);
        }
    }
}

// warp per node (strided): z[n] = dinv[n]*( sum_nbr dinv[s]*h[s] + dinv[n]*h[n] ) + bias
// accumulates BN sum/sumsq partials per block.
__global__ __launch_bounds__(256) void gather_kernel(const float* __restrict__ bias) {
    __shared__ float red[8][256];
    int lane = threadIdx.x & 31;
    int warp = threadIdx.x >> 5;
    int gw = blockIdx.x * 8 + warp;          // global warp id, stride GPART*8
    float b0 = bias[lane * 4 + 0];
    float b1 = bias[lane * 4 + 1];
    float b2 = bias[lane * 4 + 2];
    float b3 = bias[lane * 4 + 3];

    float4 s = make_float4(0.f, 0.f, 0.f, 0.f);
    float4 q = make_float4(0.f, 0.f, 0.f, 0.f);

    for (int n = gw; n < NN; n += GPART * 8) {
        int rs = d_rs[n];
        int re = d_rs[n + 1];
        float dv = d_dinv[n];
        const float4* selfp = (const float4*)(d_hs + (long long)n * FD) + lane;
        float4 sv = __ldg(selfp);
        float4 acc = make_float4(sv.x * dv, sv.y * dv, sv.z * dv, sv.w * dv);

        int j = rs;
        for (; j + 4 <= re; j += 4) {
            int i0 = d_csr[j], i1 = d_csr[j + 1], i2 = d_csr[j + 2], i3 = d_csr[j + 3];
            float e0 = d_dinv[i0], e1 = d_dinv[i1], e2 = d_dinv[i2], e3 = d_dinv[i3];
            float4 v0 = __ldg((const float4*)(d_hs + (long long)i0 * FD) + lane);
            float4 v1 = __ldg((const float4*)(d_hs + (long long)i1 * FD) + lane);
            float4 v2 = __ldg((const float4*)(d_hs + (long long)i2 * FD) + lane);
            float4 v3 = __ldg((const float4*)(d_hs + (long long)i3 * FD) + lane);
            acc.x = fmaf(v0.x, e0, acc.x); acc.y = fmaf(v0.y, e0, acc.y);
            acc.z = fmaf(v0.z, e0, acc.z); acc.w = fmaf(v0.w, e0, acc.w);
            acc.x = fmaf(v1.x, e1, acc.x); acc.y = fmaf(v1.y, e1, acc.y);
            acc.z = fmaf(v1.z, e1, acc.z); acc.w = fmaf(v1.w, e1, acc.w);
            acc.x = fmaf(v2.x, e2, acc.x); acc.y = fmaf(v2.y, e2, acc.y);
            acc.z = fmaf(v2.z, e2, acc.z); acc.w = fmaf(v2.w, e2, acc.w);
            acc.x = fmaf(v3.x, e3, acc.x); acc.y = fmaf(v3.y, e3, acc.y);
            acc.z = fmaf(v3.z, e3, acc.z); acc.w = fmaf(v3.w, e3, acc.w);
        }
        for (; j < re; j++) {
            int i0 = d_csr[j];
            float e0 = d_dinv[i0];
            float4 v0 = __ldg((const float4*)(d_hs + (long long)i0 * FD) + lane);
            acc.x = fmaf(v0.x, e0, acc.x); acc.y = fmaf(v0.y, e0, acc.y);
            acc.z = fmaf(v0.z, e0, acc.z); acc.w = fmaf(v0.w, e0, acc.w);
        }

        float4 z;
        z.x = fmaf(acc.x, dv, b0);
        z.y = fmaf(acc.y, dv, b1);
        z.z = fmaf(acc.z, dv, b2);
        z.w = fmaf(acc.w, dv, b3);
        *((float4*)(d_z + (long long)n * FD) + lane) = z;

        s.x += z.x; s.y += z.y; s.z += z.z; s.w += z.w;
        q.x = fmaf(z.x, z.x, q.x); q.y = fmaf(z.y, z.y, q.y);
        q.z = fmaf(z.z, z.z, q.z); q.w = fmaf(z.w, z.w, q.w);
    }

    red[warp][lane * 4 + 0] = s.x; red[warp][lane * 4 + 1] = s.y;
    red[warp][lane * 4 + 2] = s.z; red[warp][lane * 4 + 3] = s.w;
    red[warp][128 + lane * 4 + 0] = q.x; red[warp][128 + lane * 4 + 1] = q.y;
    red[warp][128 + lane * 4 + 2] = q.z; red[warp][128 + lane * 4 + 3] = q.w;
    __syncthreads();
    int c = threadIdx.x;
    float t = 0.f;
#pragma unroll
    for (int w = 0; w < 8; w++) t += red[w][c];
    d_part[blockIdx.x * 256 + c] = t;
}

// reduce partials -> BN scale/shift for layer
__global__ void bnstats_kernel(const float* __restrict__ g, const float* __restrict__ be, int layer) {
    __shared__ float ss[128], qq[128];
    int f = blockIdx.x;
    int t = threadIdx.x;
    if (t < 128) {
        float v = 0.f;
#pragma unroll
        for (int k = 0; k < GPART / 128; k++) v += d_part[(t + 128 * k) * 256 + f];
        ss[t] = v;
    } else {
        int tt = t - 128;
        float v = 0.f;
#pragma unroll
        for (int k = 0; k < GPART / 128; k++) v += d_part[(tt + 128 * k) * 256 + 128 + f];
        qq[tt] = v;
    }
    __syncthreads();
#pragma unroll
    for (int off = 64; off > 0; off >>= 1) {
        if (t < off) ss[t] += ss[t + off];
        else if (t >= 128 && t < 128 + off) qq[t - 128] += qq[t - 128 + off];
        __syncthreads();
    }
    if (t == 0) {
        float inv_n = 1.0f / (float)NN;
        float mu = ss[0] * inv_n;
        float ms = qq[0] * inv_n;
        float var = ms - mu * mu;
        float sc = g[f] * rsqrtf(var + 1e-5f);
        d_bnscale[layer * FD + f] = sc;
        d_bnshift[layer * FD + f] = be[f] - mu * sc;
    }
}

// warp per node: pooled[batch[n]] += relu(bn1(z[n]))
__global__ __launch_bounds__(256) void pool_kernel(const void* batch) {
    long long gt = (long long)blockIdx.x * blockDim.x + threadIdx.x;
    long long n = gt >> 5;
    int lane = threadIdx.x & 31;
    if (n >= NN) return;
    int g = load_idx(batch, n);
    int f = lane * 4;
    float4 v = *(const float4*)(d_z + n * FD + f);
    float4 sc = *(const float4*)&d_bnscale[FD + f];
    float4 sh = *(const float4*)&d_bnshift[FD + f];
    v.x = fmaxf(fmaf(v.x, sc.x, sh.x), 0.f);
    v.y = fmaxf(fmaf(v.y, sc.y, sh.y), 0.f);
    v.z = fmaxf(fmaf(v.z, sc.z, sh.z), 0.f);
    v.w = fmaxf(fmaf(v.w, sc.w, sh.w), 0.f);
    red_add_v4(d_pooled + (long long)g * FD + f, v);
}

__global__ void out_kernel(const float* __restrict__ Wout, const float* __restrict__ bout,
                           float* __restrict__ out) {
    int g = blockIdx.x;
    int o = threadIdx.x;
    float inv = 1.0f / fmaxf((float)d_gcnt[g], 1.0f);
    float acc = 0.f;
#pragma unroll 8
    for (int h = 0; h < FD; h++) acc += d_pooled[g * FD + h] * Wout[h * FO + o];
    out[g * FO + o] = acc * inv + bout[o];
}

// ---------------- launch ----------------
extern "C" void kernel_launch(void* const* d_in, const int* in_sizes, int n_in,
                              void* d_out, int out_size) {
    int ii = 0;
    auto nxt = [&]() -> const void* {
        while (ii < n_in && in_sizes[ii] == 1) ii++;
        return d_in[ii++];
    };
    const float* x   = (const float*)nxt();
    const void*  ei  = nxt();
    const void*  bat = nxt();
    const float* W0  = (const float*)nxt();
    const float* b0  = (const float*)nxt();
    const float* g0  = (const float*)nxt();
    const float* be0 = (const float*)nxt();
    const float* W1  = (const float*)nxt();
    const float* b1  = (const float*)nxt();
    const float* g1  = (const float*)nxt();
    const float* be1 = (const float*)nxt();
    const float* Wo  = (const float*)nxt();
    const float* bo  = (const float*)nxt();
    float* out = (float*)d_out;

    detect_kernel<<<1, 32>>>((const unsigned int*)ei);
    zero_misc_kernel<<<(NN + 255) / 256, 256>>>();
    deg_kernel<<<(NE + 255) / 256, 256>>>(ei);
    gemm_kernel<<<(NN + 127) / 128, 256>>>(x, W0, 0);        // layer-0 GEMM (independent of degrees)
    gcount_kernel<<<(NN + 255) / 256, 256>>>(bat);
    scanA_kernel<<<NBLK, 1024>>>();
    scanB_kernel<<<1, 128>>>();
    scanC_kernel<<<NBLK, 1024>>>();
    csr_fill_kernel<<<(NE + 255) / 256, 256>>>(ei);

    gather_kernel<<<GPART, 256>>>(b0);
    bnstats_kernel<<<FD, 256>>>(g0, be0, 0);

    gemm_kernel<<<(NN + 127) / 128, 256>>>(nullptr, W1, 1);
    gather_kernel<<<GPART, 256>>>(b1);
    bnstats_kernel<<<FD, 256>>>(g1, be1, 1);

    pool_kernel<<<(int)(((long long)NN * 32 + 255) / 256), 256>>>(bat);
    out_kernel<<<NG, FO>>>(Wo, bo, out);
}

// round 10
// speedup vs baseline: 1.8409x; 1.1630x over previous
#include <cuda_runtime.h>
#include <cuda_bf16.h>
#include <cstdint>

#define NN 100000
#define NE 1600000
#define FD 128
#define NG 128
#define FO 64
#define NBLK 98            // ceil(NN/1024)
#define GPART 1024         // gather grid / #stat partials
#define GEMM_GRID 782      // ceil(NN/128)
#define LDA 136            // bf16 elements per smem row (272B, conflict-free)
#define GEMM_SMEM (4 * 128 * LDA * 2)   // 139264 B

// ---------------- device scratch ----------------
__device__ __align__(16) float d_hs[NN * FD];    // h (per layer, unscaled)
__device__ __align__(16) float d_z[NN * FD];     // pre-BN layer output
__device__ float d_dinv[NN];
__device__ int   d_degcnt[NN];
__device__ int   d_rowtmp[NN];
__device__ int   d_rs[NN + 1];
__device__ int   d_cur[NN];
__device__ int   d_csr[NE];
__device__ int   d_bsum[NBLK];
__device__ int   d_boff[128];
__device__ float d_part[GPART * 256];
__device__ float d_bnscale[2 * FD];
__device__ float d_bnshift[2 * FD];
__device__ __align__(16) float d_pooled[NG * FD];
__device__ int   d_gcnt[NG];
__device__ int   d_is64;
__device__ __align__(16) unsigned short d_whi[2][FD * FD];  // W^T split hi (bf16 bits), [n][k]
__device__ __align__(16) unsigned short d_wlo[2][FD * FD];  // W^T split lo

// ---------------- helpers ----------------
__device__ __forceinline__ uint32_t smem_to_u32(const void* p) {
    uint32_t a;
    asm("{ .reg .u64 t; cvta.to.shared.u64 t, %1; cvt.u32.u64 %0, t; }" : "=r"(a) : "l"(p));
    return a;
}
__device__ __forceinline__ void ldsm_x4(uint32_t addr, uint32_t* r) {
    asm volatile("ldmatrix.sync.aligned.m8n8.x4.shared.b16 {%0,%1,%2,%3}, [%4];"
                 : "=r"(r[0]), "=r"(r[1]), "=r"(r[2]), "=r"(r[3]) : "r"(addr));
}
__device__ __forceinline__ void ldsm_x2(uint32_t addr, uint32_t* r) {
    asm volatile("ldmatrix.sync.aligned.m8n8.x2.shared.b16 {%0,%1}, [%2];"
                 : "=r"(r[0]), "=r"(r[1]) : "r"(addr));
}
__device__ __forceinline__ void mma_bf16(float* c, const uint32_t* a, const uint32_t* b) {
    asm volatile("mma.sync.aligned.m16n8k16.row.col.f32.bf16.bf16.f32 "
                 "{%0,%1,%2,%3}, {%4,%5,%6,%7}, {%8,%9}, {%0,%1,%2,%3};"
                 : "+f"(c[0]), "+f"(c[1]), "+f"(c[2]), "+f"(c[3])
                 : "r"(a[0]), "r"(a[1]), "r"(a[2]), "r"(a[3]), "r"(b[0]), "r"(b[1]));
}
__device__ __forceinline__ int load_idx(const void* p, long long i) {
    if (d_is64) return (int)((const long long*)p)[i];
    return ((const int*)p)[i];
}
__device__ __forceinline__ void red_add_v4(float* dst, float4 v) {
    asm volatile("red.global.add.v4.f32 [%0], {%1, %2, %3, %4};"
                 :: "l"(dst), "f"(v.x), "f"(v.y), "f"(v.z), "f"(v.w) : "memory");
}
__device__ __forceinline__ uint32_t pack_bf2(float a, float b) {
    unsigned short la = __bfloat16_as_ushort(__float2bfloat16(a));
    unsigned short lb = __bfloat16_as_ushort(__float2bfloat16(b));
    return ((uint32_t)lb << 16) | la;
}
__device__ __forceinline__ float bf_res(float a) {   // a - bf16(a)
    return a - __bfloat162float(__float2bfloat16(a));
}

// ---------------- kernels ----------------

__global__ void detect_kernel(const unsigned int* ei32) {
    if (threadIdx.x == 0) {
        int is64 = 1;
        for (int i = 0; i < 128; i++)
            if (ei32[2 * i + 1] != 0u) { is64 = 0; break; }
        d_is64 = is64;
    }
}

__global__ void zero_misc_kernel() {
    int i = blockIdx.x * blockDim.x + threadIdx.x;
    if (i < NN) d_degcnt[i] = 0;
    if (i < NG * FD) d_pooled[i] = 0.0f;
    if (i < NG) d_gcnt[i] = 0;
}

// split W (fp32 [k][n]) into bf16 hi/lo transposed [n][k]
__global__ void wsplit_kernel(const float* __restrict__ W, int which) {
    int i = blockIdx.x * 256 + threadIdx.x;
    int k = i >> 7, n = i & 127;
    float w = W[i];
    __nv_bfloat16 h = __float2bfloat16(w);
    float hf = __bfloat162float(h);
    d_whi[which][n * FD + k] = __bfloat16_as_ushort(h);
    d_wlo[which][n * FD + k] = __bfloat16_as_ushort(__float2bfloat16(w - hf));
}

__global__ void deg_kernel(const void* ei) {
    int i = blockIdx.x * blockDim.x + threadIdx.x;
    if (i < NE) atomicAdd(&d_degcnt[load_idx(ei, (long long)NE + i)], 1);
}

__global__ void gcount_kernel(const void* batch) {
    int i = blockIdx.x * blockDim.x + threadIdx.x;
    if (i < NN) atomicAdd(&d_gcnt[load_idx(batch, i)], 1);
}

__global__ void scanA_kernel() {
    __shared__ int sm[1024];
    int i = blockIdx.x * 1024 + threadIdx.x;
    int v = (i < NN) ? d_degcnt[i] : 0;
    sm[threadIdx.x] = v;
    __syncthreads();
#pragma unroll
    for (int off = 1; off < 1024; off <<= 1) {
        int t = (threadIdx.x >= off) ? sm[threadIdx.x - off] : 0;
        __syncthreads();
        sm[threadIdx.x] += t;
        __syncthreads();
    }
    if (i < NN) d_rowtmp[i] = sm[threadIdx.x];
    if (threadIdx.x == 1023) d_bsum[blockIdx.x] = sm[1023];
}

__global__ void scanB_kernel() {
    __shared__ int sm[128];
    int t = threadIdx.x;
    sm[t] = (t < NBLK) ? d_bsum[t] : 0;
    __syncthreads();
#pragma unroll
    for (int off = 1; off < 128; off <<= 1) {
        int v = (t >= off) ? sm[t - off] : 0;
        __syncthreads();
        sm[t] += v;
        __syncthreads();
    }
    d_boff[t] = sm[t];
}

__global__ void scanC_kernel() {
    int i = blockIdx.x * 1024 + threadIdx.x;
    if (i >= NN) return;
    int blk = blockIdx.x;
    int off = (blk == 0) ? 0 : d_boff[blk - 1];
    int deg = d_degcnt[i];
    int incl = d_rowtmp[i] + off;
    d_rs[i + 1] = incl;
    d_cur[i] = incl - deg;
    d_dinv[i] = rsqrtf((float)(deg + 1));
    if (i == 0) d_rs[0] = 0;
}

__global__ void csr_fill_kernel(const void* ei) {
    int i = blockIdx.x * blockDim.x + threadIdx.x;
    if (i >= NE) return;
    int s = load_idx(ei, i);
    int d = load_idx(ei, (long long)NE + i);
    int pos = atomicAdd(&d_cur[d], 1);
    d_csr[pos] = s;
}

// bf16-split tensor-core GEMM via mma.sync: d_hs[tile] = bnrelu?(A) @ W
// M=128 tile, N=128, K=128. 8 warps: warp tile 32(M) x 64(N), m16n8k16 atoms.
__global__ __launch_bounds__(256) void gemm_mma_kernel(const float* __restrict__ Aext, int layer) {
    extern __shared__ __align__(16) char sm_raw[];
    unsigned short* sAhi = (unsigned short*)sm_raw;          // [128][LDA]
    unsigned short* sAlo = sAhi + 128 * LDA;
    unsigned short* sBhi = sAlo + 128 * LDA;                 // W^T [n][k]
    unsigned short* sBlo = sBhi + 128 * LDA;

    const float* A = (layer == 0) ? Aext : d_z;
    int tid = threadIdx.x;
    int lane = tid & 31, wid = tid >> 5;
    int bm = blockIdx.x * 128;

    // ---- stage A (fp32 load, optional BN+ReLU, bf16 hi/lo split) and B (copy) ----
    {
        int row = tid & 127;
        int half = tid >> 7;                 // 0: cols 0-63, 1: cols 64-127
        int grow = bm + row;
        const float* ap = A + (long long)grow * FD;
#pragma unroll
        for (int g = 0; g < 8; g++) {
            int c = half * 64 + g * 8;
            float4 v0 = make_float4(0.f, 0.f, 0.f, 0.f);
            float4 v1 = v0;
            if (grow < NN) {
                v0 = *(const float4*)(ap + c);
                v1 = *(const float4*)(ap + c + 4);
            }
            if (layer == 1) {
                float4 sc0 = *(const float4*)&d_bnscale[c];
                float4 sh0 = *(const float4*)&d_bnshift[c];
                float4 sc1 = *(const float4*)&d_bnscale[c + 4];
                float4 sh1 = *(const float4*)&d_bnshift[c + 4];
                v0.x = fmaxf(fmaf(v0.x, sc0.x, sh0.x), 0.f);
                v0.y = fmaxf(fmaf(v0.y, sc0.y, sh0.y), 0.f);
                v0.z = fmaxf(fmaf(v0.z, sc0.z, sh0.z), 0.f);
                v0.w = fmaxf(fmaf(v0.w, sc0.w, sh0.w), 0.f);
                v1.x = fmaxf(fmaf(v1.x, sc1.x, sh1.x), 0.f);
                v1.y = fmaxf(fmaf(v1.y, sc1.y, sh1.y), 0.f);
                v1.z = fmaxf(fmaf(v1.z, sc1.z, sh1.z), 0.f);
                v1.w = fmaxf(fmaf(v1.w, sc1.w, sh1.w), 0.f);
            }
            uint4 hi, lo;
            hi.x = pack_bf2(v0.x, v0.y); hi.y = pack_bf2(v0.z, v0.w);
            hi.z = pack_bf2(v1.x, v1.y); hi.w = pack_bf2(v1.z, v1.w);
            lo.x = pack_bf2(bf_res(v0.x), bf_res(v0.y));
            lo.y = pack_bf2(bf_res(v0.z), bf_res(v0.w));
            lo.z = pack_bf2(bf_res(v1.x), bf_res(v1.y));
            lo.w = pack_bf2(bf_res(v1.z), bf_res(v1.w));
            *(uint4*)(sAhi + row * LDA + c) = hi;
            *(uint4*)(sAlo + row * LDA + c) = lo;
        }
        const unsigned short* wh = &d_whi[layer][row * FD + half * 64];
        const unsigned short* wl = &d_wlo[layer][row * FD + half * 64];
#pragma unroll
        for (int g = 0; g < 8; g++) {
            *(uint4*)(sBhi + row * LDA + half * 64 + g * 8) = *(const uint4*)(wh + g * 8);
            *(uint4*)(sBlo + row * LDA + half * 64 + g * 8) = *(const uint4*)(wl + g * 8);
        }
    }
    __syncthreads();

    // ---- compute ----
    int wm = wid & 3, wn = wid >> 2;
    int m0 = wm * 32, n0 = wn * 64;

    float acc[2][8][4];
#pragma unroll
    for (int im = 0; im < 2; im++)
#pragma unroll
        for (int in = 0; in < 8; in++)
#pragma unroll
            for (int c = 0; c < 4; c++) acc[im][in][c] = 0.f;

    int r8 = lane & 7;
    int g1 = (lane >> 3) & 1;
    int g2 = lane >> 4;
    // A lane address: row = m0 + im*16 + g1*8 + r8 ; col = g2*8 (+16 per k-step)
    uint32_t aHi = smem_to_u32(sAhi) + (uint32_t)(((m0 + g1 * 8 + r8) * LDA + g2 * 8) * 2);
    uint32_t aLo = aHi + 128 * LDA * 2;
    // B lane address: row = n0 + in*8 + r8 ; col = g1*8 (+16 per k-step); lanes>=16 mirror
    uint32_t bHi = smem_to_u32(sBhi) + (uint32_t)(((n0 + r8) * LDA + g1 * 8) * 2);
    uint32_t bLo = bHi + 128 * LDA * 2;

#pragma unroll
    for (int ks = 0; ks < 8; ks++) {
        uint32_t ko = ks * 32;               // 16 bf16 = 32 bytes
        uint32_t ahi[2][4], alo[2][4];
        ldsm_x4(aHi + ko, ahi[0]);
        ldsm_x4(aHi + 16 * LDA * 2 + ko, ahi[1]);
        ldsm_x4(aLo + ko, alo[0]);
        ldsm_x4(aLo + 16 * LDA * 2 + ko, alo[1]);
        uint32_t bhi[8][2], blo[8][2];
#pragma unroll
        for (int in = 0; in < 8; in++) {
            ldsm_x2(bHi + in * (8 * LDA * 2) + ko, bhi[in]);
            ldsm_x2(bLo + in * (8 * LDA * 2) + ko, blo[in]);
        }
#pragma unroll
        for (int im = 0; im < 2; im++)
#pragma unroll
            for (int in = 0; in < 8; in++) {
                mma_bf16(acc[im][in], ahi[im], bhi[in]);
                mma_bf16(acc[im][in], ahi[im], blo[in]);
                mma_bf16(acc[im][in], alo[im], bhi[in]);
            }
    }

    // ---- epilogue: acc -> d_hs ----
    int rlo = lane >> 2;
    int cbase = (lane & 3) * 2;
#pragma unroll
    for (int im = 0; im < 2; im++) {
        int row0 = bm + m0 + im * 16 + rlo;
        int row1 = row0 + 8;
#pragma unroll
        for (int in = 0; in < 8; in++) {
            int col = n0 + in * 8 + cbase;
            if (row0 < NN) {
                float2 v = make_float2(acc[im][in][0], acc[im][in][1]);
                *(float2*)(d_hs + (long long)row0 * FD + col) = v;
            }
            if (row1 < NN) {
                float2 v = make_float2(acc[im][in][2], acc[im][in][3]);
                *(float2*)(d_hs + (long long)row1 * FD + col) = v;
            }
        }
    }
}

// warp per node (strided): z[n] = dinv[n]*( sum_nbr dinv[s]*h[s] + dinv[n]*h[n] ) + bias
__global__ __launch_bounds__(256) void gather_kernel(const float* __restrict__ bias) {
    __shared__ float red[8][256];
    int lane = threadIdx.x & 31;
    int warp = threadIdx.x >> 5;
    int gw = blockIdx.x * 8 + warp;
    float b0 = bias[lane * 4 + 0];
    float b1 = bias[lane * 4 + 1];
    float b2 = bias[lane * 4 + 2];
    float b3 = bias[lane * 4 + 3];

    float4 s = make_float4(0.f, 0.f, 0.f, 0.f);
    float4 q = make_float4(0.f, 0.f, 0.f, 0.f);

    for (int n = gw; n < NN; n += GPART * 8) {
        int rs = d_rs[n];
        int re = d_rs[n + 1];
        float dv = d_dinv[n];
        float4 sv = __ldg((const float4*)(d_hs + (long long)n * FD) + lane);
        float4 acc = make_float4(sv.x * dv, sv.y * dv, sv.z * dv, sv.w * dv);

        int j = rs;
        for (; j + 4 <= re; j += 4) {
            int i0 = d_csr[j], i1 = d_csr[j + 1], i2 = d_csr[j + 2], i3 = d_csr[j + 3];
            float e0 = d_dinv[i0], e1 = d_dinv[i1], e2 = d_dinv[i2], e3 = d_dinv[i3];
            float4 v0 = __ldg((const float4*)(d_hs + (long long)i0 * FD) + lane);
            float4 v1 = __ldg((const float4*)(d_hs + (long long)i1 * FD) + lane);
            float4 v2 = __ldg((const float4*)(d_hs + (long long)i2 * FD) + lane);
            float4 v3 = __ldg((const float4*)(d_hs + (long long)i3 * FD) + lane);
            acc.x = fmaf(v0.x, e0, acc.x); acc.y = fmaf(v0.y, e0, acc.y);
            acc.z = fmaf(v0.z, e0, acc.z); acc.w = fmaf(v0.w, e0, acc.w);
            acc.x = fmaf(v1.x, e1, acc.x); acc.y = fmaf(v1.y, e1, acc.y);
            acc.z = fmaf(v1.z, e1, acc.z); acc.w = fmaf(v1.w, e1, acc.w);
            acc.x = fmaf(v2.x, e2, acc.x); acc.y = fmaf(v2.y, e2, acc.y);
            acc.z = fmaf(v2.z, e2, acc.z); acc.w = fmaf(v2.w, e2, acc.w);
            acc.x = fmaf(v3.x, e3, acc.x); acc.y = fmaf(v3.y, e3, acc.y);
            acc.z = fmaf(v3.z, e3, acc.z); acc.w = fmaf(v3.w, e3, acc.w);
        }
        for (; j < re; j++) {
            int i0 = d_csr[j];
            float e0 = d_dinv[i0];
            float4 v0 = __ldg((const float4*)(d_hs + (long long)i0 * FD) + lane);
            acc.x = fmaf(v0.x, e0, acc.x); acc.y = fmaf(v0.y, e0, acc.y);
            acc.z = fmaf(v0.z, e0, acc.z); acc.w = fmaf(v0.w, e0, acc.w);
        }

        float4 z;
        z.x = fmaf(acc.x, dv, b0);
        z.y = fmaf(acc.y, dv, b1);
        z.z = fmaf(acc.z, dv, b2);
        z.w = fmaf(acc.w, dv, b3);
        *((float4*)(d_z + (long long)n * FD) + lane) = z;

        s.x += z.x; s.y += z.y; s.z += z.z; s.w += z.w;
        q.x = fmaf(z.x, z.x, q.x); q.y = fmaf(z.y, z.y, q.y);
        q.z = fmaf(z.z, z.z, q.z); q.w = fmaf(z.w, z.w, q.w);
    }

    red[warp][lane * 4 + 0] = s.x; red[warp][lane * 4 + 1] = s.y;
    red[warp][lane * 4 + 2] = s.z; red[warp][lane * 4 + 3] = s.w;
    red[warp][128 + lane * 4 + 0] = q.x; red[warp][128 + lane * 4 + 1] = q.y;
    red[warp][128 + lane * 4 + 2] = q.z; red[warp][128 + lane * 4 + 3] = q.w;
    __syncthreads();
    int c = threadIdx.x;
    float t = 0.f;
#pragma unroll
    for (int w = 0; w < 8; w++) t += red[w][c];
    d_part[blockIdx.x * 256 + c] = t;
}

__global__ void bnstats_kernel(const float* __restrict__ g, const float* __restrict__ be, int layer) {
    __shared__ float ss[128], qq[128];
    int f = blockIdx.x;
    int t = threadIdx.x;
    if (t < 128) {
        float v = 0.f;
#pragma unroll
        for (int k = 0; k < GPART / 128; k++) v += d_part[(t + 128 * k) * 256 + f];
        ss[t] = v;
    } else {
        int tt = t - 128;
        float v = 0.f;
#pragma unroll
        for (int k = 0; k < GPART / 128; k++) v += d_part[(tt + 128 * k) * 256 + 128 + f];
        qq[tt] = v;
    }
    __syncthreads();
#pragma unroll
    for (int off = 64; off > 0; off >>= 1) {
        if (t < off) ss[t] += ss[t + off];
        else if (t >= 128 && t < 128 + off) qq[t - 128] += qq[t - 128 + off];
        __syncthreads();
    }
    if (t == 0) {
        float inv_n = 1.0f / (float)NN;
        float mu = ss[0] * inv_n;
        float ms = qq[0] * inv_n;
        float var = ms - mu * mu;
        float sc = g[f] * rsqrtf(var + 1e-5f);
        d_bnscale[layer * FD + f] = sc;
        d_bnshift[layer * FD + f] = be[f] - mu * sc;
    }
}

__global__ __launch_bounds__(256) void pool_kernel(const void* batch) {
    long long gt = (long long)blockIdx.x * blockDim.x + threadIdx.x;
    long long n = gt >> 5;
    int lane = threadIdx.x & 31;
    if (n >= NN) return;
    int g = load_idx(batch, n);
    int f = lane * 4;
    float4 v = *(const float4*)(d_z + n * FD + f);
    float4 sc = *(const float4*)&d_bnscale[FD + f];
    float4 sh = *(const float4*)&d_bnshift[FD + f];
    v.x = fmaxf(fmaf(v.x, sc.x, sh.x), 0.f);
    v.y = fmaxf(fmaf(v.y, sc.y, sh.y), 0.f);
    v.z = fmaxf(fmaf(v.z, sc.z, sh.z), 0.f);
    v.w = fmaxf(fmaf(v.w, sc.w, sh.w), 0.f);
    red_add_v4(d_pooled + (long long)g * FD + f, v);
}

__global__ void out_kernel(const float* __restrict__ Wout, const float* __restrict__ bout,
                           float* __restrict__ out) {
    int g = blockIdx.x;
    int o = threadIdx.x;
    float inv = 1.0f / fmaxf((float)d_gcnt[g], 1.0f);
    float acc = 0.f;
#pragma unroll 8
    for (int h = 0; h < FD; h++) acc += d_pooled[g * FD + h] * Wout[h * FO + o];
    out[g * FO + o] = acc * inv + bout[o];
}

// ---------------- launch ----------------
extern "C" void kernel_launch(void* const* d_in, const int* in_sizes, int n_in,
                              void* d_out, int out_size) {
    int ii = 0;
    auto nxt = [&]() -> const void* {
        while (ii < n_in && in_sizes[ii] == 1) ii++;
        return d_in[ii++];
    };
    const float* x   = (const float*)nxt();
    const void*  ei  = nxt();
    const void*  bat = nxt();
    const float* W0  = (const float*)nxt();
    const float* b0  = (const float*)nxt();
    const float* g0  = (const float*)nxt();
    const float* be0 = (const float*)nxt();
    const float* W1  = (const float*)nxt();
    const float* b1  = (const float*)nxt();
    const float* g1  = (const float*)nxt();
    const float* be1 = (const float*)nxt();
    const float* Wo  = (const float*)nxt();
    const float* bo  = (const float*)nxt();
    float* out = (float*)d_out;

    static int smem_set = 0;
    if (!smem_set) {
        cudaFuncSetAttribute(gemm_mma_kernel, cudaFuncAttributeMaxDynamicSharedMemorySize, GEMM_SMEM);
        smem_set = 1;
    }

    detect_kernel<<<1, 32>>>((const unsigned int*)ei);
    zero_misc_kernel<<<(NN + 255) / 256, 256>>>();
    wsplit_kernel<<<64, 256>>>(W0, 0);
    wsplit_kernel<<<64, 256>>>(W1, 1);
    deg_kernel<<<(NE + 255) / 256, 256>>>(ei);
    gemm_mma_kernel<<<GEMM_GRID, 256, GEMM_SMEM>>>(x, 0);    // layer-0 GEMM
    gcount_kernel<<<(NN + 255) / 256, 256>>>(bat);
    scanA_kernel<<<NBLK, 1024>>>();
    scanB_kernel<<<1, 128>>>();
    scanC_kernel<<<NBLK, 1024>>>();
    csr_fill_kernel<<<(NE + 255) / 256, 256>>>(ei);

    gather_kernel<<<GPART, 256>>>(b0);
    bnstats_kernel<<<FD, 256>>>(g0, be0, 0);

    gemm_mma_kernel<<<GEMM_GRID, 256, GEMM_SMEM>>>(nullptr, 1);
    gather_kernel<<<GPART, 256>>>(b1);
    bnstats_kernel<<<FD, 256>>>(g1, be1, 1);

    pool_kernel<<<(int)(((long long)NN * 32 + 255) / 256), 256>>>(bat);
    out_kernel<<<NG, FO>>>(Wo, bo, out);
}